// round 9
// baseline (speedup 1.0000x reference)
#include <cuda_runtime.h>
#include <cstdint>

#define B 2
#define N 2048
#define C 768
#define CG 192                     // C/4 float4 groups
#define G 256                      // 2 CTAs/SM, all co-resident
#define T 256
#define ROWS_PER 16                // X rows per CTA chunk
#define XCHUNK_BYTES (ROWS_PER * C * 4)          // 49152
#define SH_OFF XCHUNK_BYTES
#define SMEM_BYTES (XCHUNK_BYTES + 2 * CG * 16)  // 55296
#define NGRP 32                    // barrier groups (8 CTAs each)

__device__ float4 g_part[B][128][CG];   // P1: 128 partial colsums per batch
__device__ float  g_s[B][C];
__device__ float4 g_vpart[B][G][CG];
__device__ float  g_v[B][C];

// Barrier state: every counter on its OWN 128B line (monotonic, replay-safe).
struct __align__(128) Cnt { unsigned v; unsigned pad[31]; };
__device__ Cnt g_grp[4][NGRP];          // per-group arrival counters
__device__ Cnt g_root[4];               // root arrival counters
__device__ Cnt g_rel[4][NGRP];          // per-group release flags

__device__ __forceinline__ float4 f4add(float4 a, float4 b) {
    return make_float4(a.x + b.x, a.y + b.y, a.z + b.z, a.w + b.w);
}
__device__ __forceinline__ float4 f4fma(float4 a, float s, float4 acc) {
    return make_float4(fmaf(a.x, s, acc.x), fmaf(a.y, s, acc.y),
                       fmaf(a.z, s, acc.z), fmaf(a.w, s, acc.w));
}

__device__ __forceinline__ uint32_t smem_u32(const void* p) {
    uint32_t a;
    asm("{ .reg .u64 t; cvta.to.shared.u64 t, %1; cvt.u32.u64 %0, t; }"
        : "=r"(a) : "l"(p));
    return a;
}

__device__ __forceinline__ void mbar_wait(uint32_t mbar, uint32_t parity) {
    asm volatile(
        "{\n\t.reg .pred P;\n"
        "W_%=:\n\t"
        "mbarrier.try_wait.parity.shared.b64 P, [%0], %1;\n\t"
        "@!P bra W_%=;\n\t}"
        :: "r"(mbar), "r"(parity) : "memory");
}

// Two-level grid barrier. Group g = ct>>3 (8 CTAs/group, 32 groups).
// Arrivals: group counter; 8th arriver hits root. Leaders (<=32) poll root;
// then bump group release flag; members (<=8) poll their flag. Monotonic
// counters everywhere -> replay-safe without reset.
__device__ __forceinline__ void grid_barrier(int i, int ct) {
    __threadfence();                     // release this thread's writes
    __syncthreads();
    if (threadIdx.x == 0) {
        int g = ct >> 3;
        unsigned base = *(volatile unsigned*)&g_rel[i][g].v;  // pre-arrival: stable
        unsigned old = atomicAdd(&g_grp[i][g].v, 1u);
        if ((old & 7u) == 7u) {          // last of my group this launch
            unsigned r = atomicAdd(&g_root[i].v, 1u);
            unsigned target = ((r >> 5) + 1u) << 5;           // (r/32+1)*32
            volatile unsigned* rp = &g_root[i].v;
            while (*rp < target) { }
            atomicAdd(&g_rel[i][g].v, 1u);
        }
        volatile unsigned* fp = &g_rel[i][g].v;
        while (*fp < base + 1u) { }
        __threadfence();                 // acquire
    }
    __syncthreads();
}

// Arrive-only: participate in the count, never wait. (Callers' groups must be
// uniformly arrive-only so no one polls their release flag.)
__device__ __forceinline__ void grid_barrier_arrive(int i, int ct) {
    __threadfence();
    __syncthreads();
    if (threadIdx.x == 0) {
        int g = ct >> 3;
        unsigned old = atomicAdd(&g_grp[i][g].v, 1u);
        if ((old & 7u) == 7u)
            atomicAdd(&g_root[i].v, 1u);
    }
}

extern __shared__ char smem_raw[];

__global__ void __launch_bounds__(T, 2)
fused_att_scores(const float4* __restrict__ X4, const float4* __restrict__ W4,
                 float* __restrict__ out) {
    float4* xbuf = (float4*)smem_raw;                 // 48 KB: this CTA's X rows
    float4* sh   = (float4*)(smem_raw + SH_OFF);      // 6 KB: s/v staging
    __shared__ uint64_t mbar_st;
    __shared__ float u0s[4], u1s[4];
    const uint32_t mbar = smem_u32(&mbar_st);
    const uint32_t xbuf_a = smem_u32(xbuf);
    const int ct  = blockIdx.x;
    const int tid = threadIdx.x;
    const bool reducer = (ct < 32);      // groups 0-3: all members are reducers

    const int b = ct & 1, chunk = ct >> 1;            // 128 chunks per batch
    const char* xsrc = (const char*)(X4 + ((size_t)b * N + chunk * ROWS_PER) * CG);

    // ---- P1: one TMA bulk copy of 16 X rows -> smem; reduce -> g_part. ----
    if (tid == 0) {
        asm volatile("mbarrier.init.shared.b64 [%0], 1;" :: "r"(mbar) : "memory");
        asm volatile("fence.proxy.async.shared::cta;" ::: "memory");
        asm volatile(
            "mbarrier.arrive.expect_tx.shared.b64 _, [%0], %1;"
            :: "r"(mbar), "r"((uint32_t)XCHUNK_BYTES) : "memory");
        asm volatile(
            "cp.async.bulk.shared::cta.global.mbarrier::complete_tx::bytes "
            "[%0], [%1], %2, [%3];"
            :: "r"(xbuf_a), "l"(xsrc), "r"((uint32_t)XCHUNK_BYTES), "r"(mbar)
            : "memory");
    }
    __syncthreads();                 // mbar init visible to all waiters
    mbar_wait(mbar, 0);
    if (tid < CG) {
        float4 a0 = make_float4(0.f, 0.f, 0.f, 0.f), a1 = a0;
#pragma unroll
        for (int r = 0; r < ROWS_PER; r += 2) {
            a0 = f4add(a0, xbuf[r * CG + tid]);
            a1 = f4add(a1, xbuf[(r + 1) * CG + tid]);
        }
        g_part[b][chunk][tid] = f4add(a0, a1);
    }
    if (reducer) grid_barrier(0, ct); else grid_barrier_arrive(0, ct);

    // ---- P2: reduce 128 partials -> s. 32 CTAs. ----
    if (reducer) {
        int bb = ct & 1, qs = ct >> 1;                // qs in [0,16)
        int base = qs * 12;
        if (tid < 192) {
            int gi = tid % 12, sl = tid / 12;         // 16 slices of 8 partials
            float4 acc = make_float4(0.f, 0.f, 0.f, 0.f);
#pragma unroll
            for (int k = 0; k < 8; ++k)
                acc = f4add(acc, g_part[bb][sl * 8 + k][base + gi]);
            sh[tid] = acc;
        }
        __syncthreads();
        if (tid < 12) {
            float4 v = make_float4(0.f, 0.f, 0.f, 0.f);
#pragma unroll
            for (int s = 0; s < 16; ++s)
                v = f4add(v, sh[s * 12 + tid]);
            ((float4*)g_s[bb])[base + tid] = v;
        }
    }
    grid_barrier(1, ct);                              // everyone needs s

    // ---- P3 (fused rank-1): u_j = Wk_j.s; vpart += u_j * Wq_j (3 rows). ----
    {
        for (int i = tid; i < 2 * CG; i += T)         // stage s (both batches)
            sh[i] = (i < CG) ? ((const float4*)g_s[0])[i]
                             : ((const float4*)g_s[1])[i - CG];
        __syncthreads();
        int wid = tid >> 5, lane = tid & 31;
        int j0 = ct * 3;
        if (wid < 3) {
            int j = j0 + wid;
            const float4* row = W4 + (size_t)(C + j) * CG;   // Wk
            float a0 = 0.f, a1 = 0.f;
#pragma unroll
            for (int k = 0; k < 6; ++k) {
                int c4 = lane + k * 32;
                float4 w  = row[c4];
                float4 v0 = sh[c4];
                float4 v1 = sh[CG + c4];
                a0 += w.x * v0.x + w.y * v0.y + w.z * v0.z + w.w * v0.w;
                a1 += w.x * v1.x + w.y * v1.y + w.z * v1.z + w.w * v1.w;
            }
#pragma unroll
            for (int o = 16; o > 0; o >>= 1) {
                a0 += __shfl_down_sync(0xFFFFFFFFu, a0, o);
                a1 += __shfl_down_sync(0xFFFFFFFFu, a1, o);
            }
            if (lane == 0) { u0s[wid] = a0; u1s[wid] = a1; }
        }
        __syncthreads();
        if (tid < CG) {
            float4 a0 = make_float4(0.f, 0.f, 0.f, 0.f);
            float4 a1 = make_float4(0.f, 0.f, 0.f, 0.f);
#pragma unroll
            for (int jj = 0; jj < 3; ++jj) {
                float4 w = W4[(size_t)(j0 + jj) * CG + tid]; // Wq
                a0 = f4fma(w, u0s[jj], a0);
                a1 = f4fma(w, u1s[jj], a1);
            }
            g_vpart[0][ct][tid] = a0;
            g_vpart[1][ct][tid] = a1;
        }
    }
    if (reducer) grid_barrier(2, ct); else grid_barrier_arrive(2, ct);

    // ---- P4: reduce G partials -> v. 32 CTAs. ----
    if (reducer) {
        int bb = ct & 1, qs = ct >> 1;
        int base = qs * 12;
        if (tid < 192) {
            int gi = tid % 12, sl = tid / 12;         // 16 slices of 16 partials
            float4 acc = make_float4(0.f, 0.f, 0.f, 0.f);
#pragma unroll
            for (int k = 0; k < 16; ++k)
                acc = f4add(acc, g_vpart[bb][sl * 16 + k][base + gi]);
            sh[tid] = acc;
        }
        __syncthreads();
        if (tid < 12) {
            float4 v = make_float4(0.f, 0.f, 0.f, 0.f);
#pragma unroll
            for (int s = 0; s < 16; ++s)
                v = f4add(v, sh[s * 12 + tid]);
            ((float4*)g_v[bb])[base + tid] = v;
        }
    }
    grid_barrier(3, ct);                              // everyone needs v

    // ---- P5: scores from the X rows still in smem (no re-read). ----
    {
        if (tid < CG) sh[tid] = ((const float4*)g_v[b])[tid];
        __syncthreads();
        int wid = tid >> 5, lane = tid & 31;
        int nbase = chunk * ROWS_PER + wid * 2;
        float a[2];
#pragma unroll
        for (int r = 0; r < 2; ++r) {
            const float4* x = xbuf + (wid * 2 + r) * CG;
            float acc = 0.f;
#pragma unroll
            for (int k = 0; k < 6; ++k) {
                int c4 = lane + k * 32;
                float4 xv = x[c4];
                float4 vv = sh[c4];
                acc += xv.x * vv.x + xv.y * vv.y + xv.z * vv.z + xv.w * vv.w;
            }
            a[r] = acc;
        }
#pragma unroll
        for (int o = 16; o > 0; o >>= 1) {
#pragma unroll
            for (int r = 0; r < 2; ++r)
                a[r] += __shfl_down_sync(0xFFFFFFFFu, a[r], o);
        }
        if (lane == 0) {
#pragma unroll
            for (int r = 0; r < 2; ++r)
                out[b * N + nbase + r] = 0.125f * a[r];
        }
    }
}

extern "C" void kernel_launch(void* const* d_in, const int* in_sizes, int n_in,
                              void* d_out, int out_size) {
    const float4* X4 = (const float4*)d_in[0];  // [2, 2048, 768] f32
    const float4* W4 = (const float4*)d_in[1];  // [1536, 768] f32
    float* out = (float*)d_out;                 // [2, 2048] f32
    (void)in_sizes; (void)n_in; (void)out_size;

    cudaFuncSetAttribute(fused_att_scores,
                         cudaFuncAttributeMaxDynamicSharedMemorySize, SMEM_BYTES);
    fused_att_scores<<<G, T, SMEM_BYTES>>>(X4, W4, out);
}

// round 10
// speedup vs baseline: 1.2448x; 1.2448x over previous
#include <cuda_runtime.h>
#include <cstdint>

#define B 2
#define N 2048
#define C 768
#define CG 192                     // C/4 float4 groups
#define G 256                      // 2 CTAs/SM, all co-resident
#define T 256
#define ROWS_PER 16                // X rows per CTA chunk
#define XCHUNK_BYTES (ROWS_PER * C * 4)          // 49152
#define WHALF_BYTES (3 * C * 4)                  // 3 W rows = 9216
#define WBUF_OFF XCHUNK_BYTES
#define SH_OFF (XCHUNK_BYTES + 2 * WHALF_BYTES)  // 67584
#define SMEM_BYTES (SH_OFF + 2 * CG * 16)        // 73728

__device__ float4 g_part[B][128][CG];   // P1: 128 partial colsums per batch
__device__ float  g_s[B][C];
__device__ float4 g_vpart[B][G][CG];
__device__ float  g_v[B][C];

// Flat barrier counters, each on its own 128B line (monotonic, replay-safe).
struct __align__(128) Cnt { unsigned v; unsigned pad[31]; };
__device__ Cnt g_bar4[4];

__device__ __forceinline__ float4 f4add(float4 a, float4 b) {
    return make_float4(a.x + b.x, a.y + b.y, a.z + b.z, a.w + b.w);
}
__device__ __forceinline__ float4 f4fma(float4 a, float s, float4 acc) {
    return make_float4(fmaf(a.x, s, acc.x), fmaf(a.y, s, acc.y),
                       fmaf(a.z, s, acc.z), fmaf(a.w, s, acc.w));
}

__device__ __forceinline__ uint32_t smem_u32(const void* p) {
    uint32_t a;
    asm("{ .reg .u64 t; cvta.to.shared.u64 t, %1; cvt.u32.u64 %0, t; }"
        : "=r"(a) : "l"(p));
    return a;
}

__device__ __forceinline__ void mbar_wait(uint32_t mbar, uint32_t parity) {
    asm volatile(
        "{\n\t.reg .pred P;\n"
        "W_%=:\n\t"
        "mbarrier.try_wait.parity.shared.b64 P, [%0], %1;\n\t"
        "@!P bra W_%=;\n\t}"
        :: "r"(mbar), "r"(parity) : "memory");
}

__device__ __forceinline__ void grid_barrier(int i) {
    __threadfence();
    __syncthreads();
    if (threadIdx.x == 0) {
        unsigned old = atomicAdd(&g_bar4[i].v, 1u);
        unsigned target = (old / G + 1u) * G;
        volatile unsigned* p = &g_bar4[i].v;
        while (*p < target) { }
        __threadfence();
    }
    __syncthreads();
}
__device__ __forceinline__ void grid_barrier_arrive(int i) {
    __threadfence();
    __syncthreads();
    if (threadIdx.x == 0)
        atomicAdd(&g_bar4[i].v, 1u);
}

extern __shared__ char smem_raw[];

__global__ void __launch_bounds__(T, 2)
fused_att_scores(const float4* __restrict__ X4, const float4* __restrict__ W4,
                 float* __restrict__ out) {
    float4* xbuf = (float4*)smem_raw;                       // 48 KB X rows
    float4* wkbuf = (float4*)(smem_raw + WBUF_OFF);         // 9 KB: 3 Wk rows
    float4* wqbuf = (float4*)(smem_raw + WBUF_OFF + WHALF_BYTES); // 9 KB: 3 Wq rows
    float4* sh   = (float4*)(smem_raw + SH_OFF);            // 6 KB s/v staging
    __shared__ uint64_t mbar_x, mbar_w;
    __shared__ float u0s[4], u1s[4];
    const uint32_t mbx = smem_u32(&mbar_x);
    const uint32_t mbw = smem_u32(&mbar_w);
    const int ct  = blockIdx.x;
    const int tid = threadIdx.x;
    const bool reducer = (ct < 32);

    const int b = ct & 1, chunk = ct >> 1;                  // 128 chunks/batch
    const int j0 = ct * 3;
    const char* xsrc  = (const char*)(X4 + ((size_t)b * N + chunk * ROWS_PER) * CG);
    const char* wksrc = (const char*)(W4 + (size_t)(C + j0) * CG);
    const char* wqsrc = (const char*)(W4 + (size_t)j0 * CG);

    // ---- t=0: issue BOTH bulk copies (X chunk + this CTA's 6 W rows). ----
    if (tid == 0) {
        asm volatile("mbarrier.init.shared.b64 [%0], 1;" :: "r"(mbx) : "memory");
        asm volatile("mbarrier.init.shared.b64 [%0], 1;" :: "r"(mbw) : "memory");
        asm volatile("fence.proxy.async.shared::cta;" ::: "memory");
        asm volatile("mbarrier.arrive.expect_tx.shared.b64 _, [%0], %1;"
                     :: "r"(mbx), "r"((uint32_t)XCHUNK_BYTES) : "memory");
        asm volatile(
            "cp.async.bulk.shared::cta.global.mbarrier::complete_tx::bytes "
            "[%0], [%1], %2, [%3];"
            :: "r"(smem_u32(xbuf)), "l"(xsrc), "r"((uint32_t)XCHUNK_BYTES), "r"(mbx)
            : "memory");
        asm volatile("mbarrier.arrive.expect_tx.shared.b64 _, [%0], %1;"
                     :: "r"(mbw), "r"((uint32_t)(2 * WHALF_BYTES)) : "memory");
        asm volatile(
            "cp.async.bulk.shared::cta.global.mbarrier::complete_tx::bytes "
            "[%0], [%1], %2, [%3];"
            :: "r"(smem_u32(wkbuf)), "l"(wksrc), "r"((uint32_t)WHALF_BYTES), "r"(mbw)
            : "memory");
        asm volatile(
            "cp.async.bulk.shared::cta.global.mbarrier::complete_tx::bytes "
            "[%0], [%1], %2, [%3];"
            :: "r"(smem_u32(wqbuf)), "l"(wqsrc), "r"((uint32_t)WHALF_BYTES), "r"(mbw)
            : "memory");
    }
    __syncthreads();                 // mbar inits visible

    // ---- P1: wait X, reduce 16 rows -> g_part. ----
    mbar_wait(mbx, 0);
    if (tid < CG) {
        float4 a0 = make_float4(0.f, 0.f, 0.f, 0.f), a1 = a0;
#pragma unroll
        for (int r = 0; r < ROWS_PER; r += 2) {
            a0 = f4add(a0, xbuf[r * CG + tid]);
            a1 = f4add(a1, xbuf[(r + 1) * CG + tid]);
        }
        g_part[b][chunk][tid] = f4add(a0, a1);
    }
    if (reducer) grid_barrier(0); else grid_barrier_arrive(0);

    // ---- P2: reduce 128 partials -> s. 32 CTAs. ----
    if (reducer) {
        int bb = ct & 1, qs = ct >> 1;                // qs in [0,16)
        int base = qs * 12;
        if (tid < 192) {
            int gi = tid % 12, sl = tid / 12;         // 16 slices of 8 partials
            float4 acc = make_float4(0.f, 0.f, 0.f, 0.f);
#pragma unroll
            for (int k = 0; k < 8; ++k)
                acc = f4add(acc, g_part[bb][sl * 8 + k][base + gi]);
            sh[tid] = acc;
        }
        __syncthreads();
        if (tid < 12) {
            float4 v = make_float4(0.f, 0.f, 0.f, 0.f);
#pragma unroll
            for (int s = 0; s < 16; ++s)
                v = f4add(v, sh[s * 12 + tid]);
            ((float4*)g_s[bb])[base + tid] = v;
        }
    }
    grid_barrier(1);                                  // everyone needs s

    // ---- P3 (fused rank-1, W from smem): u_j = Wk_j.s; vpart += u_j*Wq_j. ----
    {
        for (int i = tid; i < 2 * CG; i += T)         // stage s (both batches)
            sh[i] = (i < CG) ? ((const float4*)g_s[0])[i]
                             : ((const float4*)g_s[1])[i - CG];
        mbar_wait(mbw, 0);                            // W prefetch done long ago
        __syncthreads();
        int wid = tid >> 5, lane = tid & 31;
        if (wid < 3) {
            const float4* row = wkbuf + wid * CG;     // Wk row (smem)
            float a0 = 0.f, a1 = 0.f;
#pragma unroll
            for (int k = 0; k < 6; ++k) {
                int c4 = lane + k * 32;
                float4 w  = row[c4];
                float4 v0 = sh[c4];
                float4 v1 = sh[CG + c4];
                a0 += w.x * v0.x + w.y * v0.y + w.z * v0.z + w.w * v0.w;
                a1 += w.x * v1.x + w.y * v1.y + w.z * v1.z + w.w * v1.w;
            }
#pragma unroll
            for (int o = 16; o > 0; o >>= 1) {
                a0 += __shfl_down_sync(0xFFFFFFFFu, a0, o);
                a1 += __shfl_down_sync(0xFFFFFFFFu, a1, o);
            }
            if (lane == 0) { u0s[wid] = a0; u1s[wid] = a1; }
        }
        __syncthreads();
        if (tid < CG) {
            float4 a0 = make_float4(0.f, 0.f, 0.f, 0.f);
            float4 a1 = make_float4(0.f, 0.f, 0.f, 0.f);
#pragma unroll
            for (int jj = 0; jj < 3; ++jj) {
                float4 w = wqbuf[jj * CG + tid];      // Wq row (smem)
                a0 = f4fma(w, u0s[jj], a0);
                a1 = f4fma(w, u1s[jj], a1);
            }
            g_vpart[0][ct][tid] = a0;
            g_vpart[1][ct][tid] = a1;
        }
    }
    if (reducer) grid_barrier(2); else grid_barrier_arrive(2);

    // ---- P4: reduce G partials -> v. 32 CTAs. ----
    if (reducer) {
        int bb = ct & 1, qs = ct >> 1;
        int base = qs * 12;
        if (tid < 192) {
            int gi = tid % 12, sl = tid / 12;         // 16 slices of 16 partials
            float4 acc = make_float4(0.f, 0.f, 0.f, 0.f);
#pragma unroll
            for (int k = 0; k < 16; ++k)
                acc = f4add(acc, g_vpart[bb][sl * 16 + k][base + gi]);
            sh[tid] = acc;
        }
        __syncthreads();
        if (tid < 12) {
            float4 v = make_float4(0.f, 0.f, 0.f, 0.f);
#pragma unroll
            for (int s = 0; s < 16; ++s)
                v = f4add(v, sh[s * 12 + tid]);
            ((float4*)g_v[bb])[base + tid] = v;
        }
    }
    grid_barrier(3);                                  // everyone needs v

    // ---- P5: scores from the X rows still in smem (no re-read). ----
    {
        if (tid < CG) sh[tid] = ((const float4*)g_v[b])[tid];
        __syncthreads();
        int wid = tid >> 5, lane = tid & 31;
        int nbase = chunk * ROWS_PER + wid * 2;
        float a[2];
#pragma unroll
        for (int r = 0; r < 2; ++r) {
            const float4* x = xbuf + (wid * 2 + r) * CG;
            float acc = 0.f;
#pragma unroll
            for (int k = 0; k < 6; ++k) {
                int c4 = lane + k * 32;
                float4 xv = x[c4];
                float4 vv = sh[c4];
                acc += xv.x * vv.x + xv.y * vv.y + xv.z * vv.z + xv.w * vv.w;
            }
            a[r] = acc;
        }
#pragma unroll
        for (int o = 16; o > 0; o >>= 1) {
#pragma unroll
            for (int r = 0; r < 2; ++r)
                a[r] += __shfl_down_sync(0xFFFFFFFFu, a[r], o);
        }
        if (lane == 0) {
#pragma unroll
            for (int r = 0; r < 2; ++r)
                out[b * N + nbase + r] = 0.125f * a[r];
        }
    }
}

extern "C" void kernel_launch(void* const* d_in, const int* in_sizes, int n_in,
                              void* d_out, int out_size) {
    const float4* X4 = (const float4*)d_in[0];  // [2, 2048, 768] f32
    const float4* W4 = (const float4*)d_in[1];  // [1536, 768] f32
    float* out = (float*)d_out;                 // [2, 2048] f32
    (void)in_sizes; (void)n_in; (void)out_size;

    cudaFuncSetAttribute(fused_att_scores,
                         cudaFuncAttributeMaxDynamicSharedMemorySize, SMEM_BYTES);
    fused_att_scores<<<G, T, SMEM_BYTES>>>(X4, W4, out);
}